// round 15
// baseline (speedup 1.0000x reference)
#include <cuda_runtime.h>

// LSTM B=8192, T=512, I=12, H=20 (i,f,g,o), zero init; Linear(H->10) on h_T.
//
// R15 = R14 + staging-overhead trims:
//  - TCH=8: two 8-step x buffers; buffer select = one pointer per 8 steps.
//  - cp_wait merged into the regular end-of-step barrier at s==7 (no extra
//    staging barriers at all); next chunk issued at s==0.
//  - Phase stagger x6 (4 barrier domains per SM offset ~300 cyc).
//  - Thread = 2 gate rows x 1 unit x 4 batches, 32 u64 weights in regs;
//    partner (lane^1) holds the other 2 gates, combined via shfl.xor(1).
//  - Block 320 thr = 2 independent 160-thr groups (named barriers), BPB=32,
//    grid=256, __launch_bounds__(320,2). 8-step fully unrolled body.

#define LSTM_H   20
#define LSTM_I   12
#define LSTM_T   512
#define BPB      32
#define THREADS  320
#define GRID     256
#define XROW     100   // floats per batch row in an x buffer: 96 data + 4 pad

typedef unsigned long long u64;
typedef unsigned int       u32;

__device__ __forceinline__ u64 pack2(float lo, float hi) {
    u64 r; asm("mov.b64 %0, {%1, %2};" : "=l"(r) : "f"(lo), "f"(hi)); return r;
}
__device__ __forceinline__ void unpack2(u64 v, float& lo, float& hi) {
    asm("mov.b64 {%0, %1}, %2;" : "=f"(lo), "=f"(hi) : "l"(v));
}
__device__ __forceinline__ u64 fma2(u64 a, u64 b, u64 c) {
    u64 r; asm("fma.rn.f32x2 %0, %1, %2, %3;" : "=l"(r) : "l"(a), "l"(b), "l"(c));
    return r;
}
__device__ __forceinline__ float hadd2(u64 v) {
    float lo, hi; unpack2(v, lo, hi); return lo + hi;
}
__device__ __forceinline__ float tanhA(float x) {
    float y; asm("tanh.approx.f32 %0, %1;" : "=f"(y) : "f"(x)); return y;
}
__device__ __forceinline__ float sigA(float x) {
    return fmaf(tanhA(0.5f * x), 0.5f, 0.5f);
}
__device__ __forceinline__ void cp_async16(u32 smem_dst, const void* gsrc) {
    asm volatile("cp.async.ca.shared.global [%0], [%1], 16;\n"
                 :: "r"(smem_dst), "l"(gsrc) : "memory");
}
__device__ __forceinline__ void cp_commit() {
    asm volatile("cp.async.commit_group;\n" ::: "memory");
}
template<int N>
__device__ __forceinline__ void cp_wait() {
    asm volatile("cp.async.wait_group %0;\n" :: "n"(N) : "memory");
}
__device__ __forceinline__ void group_bar(int id) {
    asm volatile("bar.sync %0, %1;" :: "r"(id), "r"(160) : "memory");
}

// GEMV for one batch: 2 gate rows, bias folded into acc init.
__device__ __forceinline__ void gemv2(const u64* __restrict__ xr,
                                      const u64* __restrict__ hr,
                                      const u64* w0, const u64* w1,
                                      u64 binit0, u64 binit1,
                                      float& ga, float& gb)
{
    u64 a0 = binit0, a1 = binit1;
    #pragma unroll
    for (int k = 0; k < 6; k += 2) {
        ulonglong2 xv = *(const ulonglong2*)(xr + k);
        a0 = fma2(w0[k], xv.x, a0); a0 = fma2(w0[k+1], xv.y, a0);
        a1 = fma2(w1[k], xv.x, a1); a1 = fma2(w1[k+1], xv.y, a1);
    }
    #pragma unroll
    for (int k = 0; k < 10; k += 2) {
        ulonglong2 hv = *(const ulonglong2*)(hr + k);
        a0 = fma2(w0[6+k], hv.x, a0); a0 = fma2(w0[6+k+1], hv.y, a0);
        a1 = fma2(w1[6+k], hv.x, a1); a1 = fma2(w1[6+k+1], hv.y, a1);
    }
    ga = hadd2(a0);
    gb = hadd2(a1);
}

__global__ void __launch_bounds__(THREADS, 2)
lstm_kernel(const float* __restrict__ x,
            const float* __restrict__ w_ih,
            const float* __restrict__ w_hh,
            const float* __restrict__ b_ih,
            const float* __restrict__ b_hh,
            const float* __restrict__ w_out,
            const float* __restrict__ b_out,
            float* __restrict__ out)
{
    __shared__ __align__(16) float wcomb[80 * 32];           // 10240 B
    __shared__ __align__(16) float hbuf[2][BPB * LSTM_H];    //  5120 B
    __shared__ __align__(16) float xs[2][BPB * XROW];        // 25600 B

    const int tid  = threadIdx.x;
    const int gid  = tid / 160;          // group 0/1 (owns 16 batches)
    const int ltid = tid - gid * 160;
    const int quad = tid / 40;           // 0..7 (global)
    const int r    = tid % 40;
    const int u    = r >> 1;             // unit 0..19
    const int gh   = r & 1;              // 0 -> (i,g), 1 -> (f,o)
    const int b0   = blockIdx.x * BPB;
    const int q4   = quad * 4;
    const int barid = 1 + gid;

    const int row0 = gh ? (20 + u) : u;          // f : i
    const int row1 = gh ? (60 + u) : (40 + u);   // o : g

    // ---- stage combined weight rows into SMEM ----
    for (int i = tid; i < 80 * LSTM_I; i += THREADS) {
        int rr = i / LSTM_I, k = i - rr * LSTM_I;
        wcomb[rr * 32 + k] = w_ih[i];
    }
    for (int i = tid; i < 80 * LSTM_H; i += THREADS) {
        int rr = i / LSTM_H, k = i - rr * LSTM_H;
        wcomb[rr * 32 + 12 + k] = w_hh[i];
    }
    for (int i = tid; i < BPB * LSTM_H; i += THREADS) hbuf[0][i] = 0.f;

    const u64 binit0 = pack2(b_ih[row0] + b_hh[row0], 0.f);
    const u64 binit1 = pack2(b_ih[row1] + b_hh[row1], 0.f);

    // ---- cp.async: chunk0 (steps 0-7) -> xs[0], chunk1 (8-15) -> xs[1] ----
    const float4* x4 = (const float4*)x;
    const u32 xs_base = (u32)__cvta_generic_to_shared(&xs[0][0]);
    {
        #pragma unroll 1
        for (int e = ltid; e < 16 * 24; e += 160) {
            int bl = e / 24, q = e - bl * 24;
            int b = gid * 16 + bl;
            cp_async16(xs_base + (u32)((b * XROW + q * 4) * 4),
                       x4 + (long)(b0 + b) * 1536 + q);
        }
        cp_commit();
        #pragma unroll 1
        for (int e = ltid; e < 16 * 24; e += 160) {
            int bl = e / 24, q = e - bl * 24;
            int b = gid * 16 + bl;
            cp_async16(xs_base + (u32)((BPB * XROW + b * XROW + q * 4) * 4),
                       x4 + (long)(b0 + b) * 1536 + 24 + q);
        }
        cp_commit();
    }
    cp_wait<1>();          // chunk 0 landed
    __syncthreads();       // wcomb + hbuf + chunk0 visible

    // ---- this thread's 2 gate rows into registers (32 u64 = 64 regs) ----
    u64 w0[16], w1[16];
    {
        const u64* p0 = (const u64*)&wcomb[row0 * 32];
        const u64* p1 = (const u64*)&wcomb[row1 * 32];
        #pragma unroll
        for (int k = 0; k < 16; k++) { w0[k] = p0[k]; w1[k] = p1[k]; }
    }

    // ---- phase stagger of the 4 barrier domains per SM ----
    {
        const int phase = ((blockIdx.x & 1) << 1) | gid;   // 0..3
        for (int s = 0; s < phase * 6; s++) group_bar(barid);
    }

    float c0 = 0.f, c1 = 0.f;   // my 2 owned batches: q4+2*gh, q4+2*gh+1

    // ---- main loop: 64 iterations x 8 steps; iteration m reads xs[m&1] ----
    #pragma unroll 1
    for (int m = 0; m < 64; m++) {
        const float* xsm = &xs[m & 1][0];

        #pragma unroll
        for (int s = 0; s < 8; s++) {
            if (s == 0 && m >= 1 && m <= 62) {
                // issue chunk m+1 (steps 8m+8..8m+15) into xs[(m+1)&1];
                // prior readers of that buffer finished before the last bar.
                const u32 dbase = (u32)(((m + 1) & 1) * BPB * XROW);
                const long tof  = (long)(m + 1) * 24;
                #pragma unroll 1
                for (int e = ltid; e < 16 * 24; e += 160) {
                    int bl = e / 24, q = e - bl * 24;
                    int b = gid * 16 + bl;
                    cp_async16(xs_base + (u32)((dbase + b * XROW + q * 4) * 4),
                               x4 + (long)(b0 + b) * 1536 + tof + q);
                }
                cp_commit();
            }

            const int cur = s & 1;          // compile-time in unrolled body
            const int nxt = cur ^ 1;

            const float* xb = xsm + s * 12;
            const float* hb = &hbuf[cur][0];
            float* hn = &hbuf[nxt][0];

            float gA[4], gB[4];
            #pragma unroll
            for (int j = 0; j < 4; j++)
                gemv2((const u64*)(xb + (q4 + j) * XROW),
                      (const u64*)(hb + (q4 + j) * LSTM_H),
                      w0, w1, binit0, binit1, gA[j], gB[j]);

            // ---- exchange + epilogue, pairs p=0 (j 0/2) and p=1 (j 1/3) ----
            #pragma unroll
            for (int p = 0; p < 2; p++) {
                float sendA = gh ? gA[p]     : gA[2 + p];
                float sendB = gh ? gB[p]     : gB[2 + p];
                float ownA  = gh ? gA[2 + p] : gA[p];
                float ownB  = gh ? gB[2 + p] : gB[p];
                float recvA = __shfl_xor_sync(0xffffffffu, sendA, 1);
                float recvB = __shfl_xor_sync(0xffffffffu, sendB, 1);
                float gi = gh ? recvA : ownA;
                float gg = gh ? recvB : ownB;
                float gf = gh ? ownA  : recvA;
                float go = gh ? ownB  : recvB;
                float c  = p ? c1 : c0;
                c = sigA(gf) * c + sigA(gi) * tanhA(gg);
                if (p) c1 = c; else c0 = c;
                hn[(q4 + 2 * gh + p) * LSTM_H + u] = sigA(go) * tanhA(c);
            }

            // before the last bar of the iteration, certify next chunk landed
            if (s == 7) cp_wait<0>();
            group_bar(barid);
        }
    }

    // ---- output Linear (final h in hbuf[0]: t=511 -> nxt=0; group-local) ----
    {
        const int bl = ltid / 10, k = ltid - (ltid / 10) * 10;  // 16 x 10
        const int b  = gid * 16 + bl;
        float sum = b_out[k];
        #pragma unroll
        for (int j = 0; j < LSTM_H; j++)
            sum = fmaf(hbuf[0][b * LSTM_H + j], w_out[k * LSTM_H + j], sum);
        out[(long)(b0 + b) * 10 + k] = sum;
    }
}

extern "C" void kernel_launch(void* const* d_in, const int* in_sizes, int n_in,
                              void* d_out, int out_size)
{
    const float* x     = (const float*)d_in[0];
    const float* w_ih  = (const float*)d_in[1];
    const float* w_hh  = (const float*)d_in[2];
    const float* b_ih  = (const float*)d_in[3];
    const float* b_hh  = (const float*)d_in[4];
    const float* w_out = (const float*)d_in[5];
    const float* b_out = (const float*)d_in[6];
    float* out = (float*)d_out;

    lstm_kernel<<<GRID, THREADS>>>(x, w_ih, w_hh, b_ih, b_hh, w_out, b_out, out);
}

// round 16
// speedup vs baseline: 1.6288x; 1.6288x over previous
#include <cuda_runtime.h>

// LSTM B=8192, T=512, I=12, H=20 (i,f,g,o), zero init; Linear(H->10) on h_T.
//
// R16 = R14 + merged staging barriers ONLY (revert all other R15 changes):
//  - TCH=4 double-buffer as in R14 (buf = s>>2), XROW=52, stagger x2.
//  - cp_wait<0> moved to just before the regular step-bar at s==3 / s==7;
//    next chunk issued at s==4 / s==0 with no extra barrier (the step bar
//    provides the all-threads "landed" guarantee).
//  - Thread = 2 gate rows x 1 unit x 4 batches, 32 u64 weights in regs;
//    partner (lane^1) holds the other 2 gates, combined via shfl.xor(1).
//  - Block 320 thr = 2 independent 160-thr groups (named barriers), BPB=32,
//    grid=256, __launch_bounds__(320,2). 8-step fully unrolled body.

#define LSTM_H   20
#define LSTM_I   12
#define LSTM_T   512
#define BPB      32
#define THREADS  320
#define GRID     256
#define XROW     52    // floats per batch row in xs (208B, 16B-aligned)

typedef unsigned long long u64;
typedef unsigned int       u32;

__device__ __forceinline__ u64 pack2(float lo, float hi) {
    u64 r; asm("mov.b64 %0, {%1, %2};" : "=l"(r) : "f"(lo), "f"(hi)); return r;
}
__device__ __forceinline__ void unpack2(u64 v, float& lo, float& hi) {
    asm("mov.b64 {%0, %1}, %2;" : "=f"(lo), "=f"(hi) : "l"(v));
}
__device__ __forceinline__ u64 fma2(u64 a, u64 b, u64 c) {
    u64 r; asm("fma.rn.f32x2 %0, %1, %2, %3;" : "=l"(r) : "l"(a), "l"(b), "l"(c));
    return r;
}
__device__ __forceinline__ float hadd2(u64 v) {
    float lo, hi; unpack2(v, lo, hi); return lo + hi;
}
__device__ __forceinline__ float tanhA(float x) {
    float y; asm("tanh.approx.f32 %0, %1;" : "=f"(y) : "f"(x)); return y;
}
__device__ __forceinline__ float sigA(float x) {
    return fmaf(tanhA(0.5f * x), 0.5f, 0.5f);
}
__device__ __forceinline__ void cp_async16(u32 smem_dst, const void* gsrc) {
    asm volatile("cp.async.ca.shared.global [%0], [%1], 16;\n"
                 :: "r"(smem_dst), "l"(gsrc) : "memory");
}
__device__ __forceinline__ void cp_commit() {
    asm volatile("cp.async.commit_group;\n" ::: "memory");
}
template<int N>
__device__ __forceinline__ void cp_wait() {
    asm volatile("cp.async.wait_group %0;\n" :: "n"(N) : "memory");
}
__device__ __forceinline__ void group_bar(int id) {
    asm volatile("bar.sync %0, %1;" :: "r"(id), "r"(160) : "memory");
}

// GEMV for one batch: 2 gate rows, bias folded into acc init.
__device__ __forceinline__ void gemv2(const u64* __restrict__ xr,
                                      const u64* __restrict__ hr,
                                      const u64* w0, const u64* w1,
                                      u64 binit0, u64 binit1,
                                      float& ga, float& gb)
{
    u64 a0 = binit0, a1 = binit1;
    #pragma unroll
    for (int k = 0; k < 6; k += 2) {
        ulonglong2 xv = *(const ulonglong2*)(xr + k);
        a0 = fma2(w0[k], xv.x, a0); a0 = fma2(w0[k+1], xv.y, a0);
        a1 = fma2(w1[k], xv.x, a1); a1 = fma2(w1[k+1], xv.y, a1);
    }
    #pragma unroll
    for (int k = 0; k < 10; k += 2) {
        ulonglong2 hv = *(const ulonglong2*)(hr + k);
        a0 = fma2(w0[6+k], hv.x, a0); a0 = fma2(w0[6+k+1], hv.y, a0);
        a1 = fma2(w1[6+k], hv.x, a1); a1 = fma2(w1[6+k+1], hv.y, a1);
    }
    ga = hadd2(a0);
    gb = hadd2(a1);
}

__global__ void __launch_bounds__(THREADS, 2)
lstm_kernel(const float* __restrict__ x,
            const float* __restrict__ w_ih,
            const float* __restrict__ w_hh,
            const float* __restrict__ b_ih,
            const float* __restrict__ b_hh,
            const float* __restrict__ w_out,
            const float* __restrict__ b_out,
            float* __restrict__ out)
{
    __shared__ __align__(16) float wcomb[80 * 32];           // 10240 B
    __shared__ __align__(16) float hbuf[2][BPB * LSTM_H];    //  5120 B
    __shared__ __align__(16) float xs[2][BPB * XROW];        // 13312 B

    const int tid  = threadIdx.x;
    const int gid  = tid / 160;          // group 0/1 (owns 16 batches)
    const int ltid = tid - gid * 160;
    const int quad = tid / 40;           // 0..7 (global)
    const int r    = tid % 40;
    const int u    = r >> 1;             // unit 0..19
    const int gh   = r & 1;              // 0 -> (i,g), 1 -> (f,o)
    const int b0   = blockIdx.x * BPB;
    const int q4   = quad * 4;
    const int barid = 1 + gid;

    const int row0 = gh ? (20 + u) : u;          // f : i
    const int row1 = gh ? (60 + u) : (40 + u);   // o : g

    // ---- stage combined weight rows into SMEM ----
    for (int i = tid; i < 80 * LSTM_I; i += THREADS) {
        int rr = i / LSTM_I, k = i - rr * LSTM_I;
        wcomb[rr * 32 + k] = w_ih[i];
    }
    for (int i = tid; i < 80 * LSTM_H; i += THREADS) {
        int rr = i / LSTM_H, k = i - rr * LSTM_H;
        wcomb[rr * 32 + 12 + k] = w_hh[i];
    }
    for (int i = tid; i < BPB * LSTM_H; i += THREADS) hbuf[0][i] = 0.f;

    const u64 binit0 = pack2(b_ih[row0] + b_hh[row0], 0.f);
    const u64 binit1 = pack2(b_ih[row1] + b_hh[row1], 0.f);

    // ---- cp.async: chunk0 -> xs[0], chunk1 -> xs[1] (group-local 16 batches) ----
    const float4* x4 = (const float4*)x;
    const u32 xs_base = (u32)__cvta_generic_to_shared(&xs[0][0]);
    {
        #pragma unroll 1
        for (int e = ltid; e < 16 * 12; e += 160) {
            int b = gid * 16 + e / 12, q = e - (e / 12) * 12;
            cp_async16(xs_base + (u32)((b * XROW + q * 4) * 4),
                       x4 + (long)(b0 + b) * 1536 + q);
        }
        cp_commit();
        #pragma unroll 1
        for (int e = ltid; e < 16 * 12; e += 160) {
            int b = gid * 16 + e / 12, q = e - (e / 12) * 12;
            cp_async16(xs_base + (u32)((BPB * XROW + b * XROW + q * 4) * 4),
                       x4 + (long)(b0 + b) * 1536 + 12 + q);
        }
        cp_commit();
    }
    cp_wait<1>();          // chunk 0 landed
    __syncthreads();       // wcomb + hbuf + chunk0 visible

    // ---- this thread's 2 gate rows into registers (32 u64 = 64 regs) ----
    u64 w0[16], w1[16];
    {
        const u64* p0 = (const u64*)&wcomb[row0 * 32];
        const u64* p1 = (const u64*)&wcomb[row1 * 32];
        #pragma unroll
        for (int k = 0; k < 16; k++) { w0[k] = p0[k]; w1[k] = p1[k]; }
    }

    // ---- light phase stagger of the 4 barrier domains per SM ----
    {
        const int phase = ((blockIdx.x & 1) << 1) | gid;   // 0..3
        for (int s = 0; s < phase * 2; s++) group_bar(barid);
    }

    float c0 = 0.f, c1 = 0.f;   // my 2 owned batches: q4+2*gh, q4+2*gh+1

    // ---- main loop: 64 iterations x 8 steps (2 chunks), fully unrolled ----
    // Invariants entering iteration m at s==0: chunk 2m is in buf0 and landed
    // (cp_wait before last bar of prev iteration); buf1 free.
    #pragma unroll 1
    for (int m = 0; m < 64; m++) {
        #pragma unroll
        for (int s = 0; s < 8; s++) {
            // chunk issue points (no extra barriers; step-bar provides ordering)
            if (s == 0 && m > 0) {
                // issue chunk 2m+1 -> buf1 (steps 8m+4..8m+7); prior readers
                // of buf1 finished before the bar that ended s==7 of m-1.
                const long tof = (long)(8 * m + 4) * 3;
                #pragma unroll 1
                for (int e = ltid; e < 16 * 12; e += 160) {
                    int b = gid * 16 + e / 12, q = e - (e / 12) * 12;
                    cp_async16(xs_base + (u32)((BPB * XROW + b * XROW + q * 4) * 4),
                               x4 + (long)(b0 + b) * 1536 + tof + q);
                }
                cp_commit();
            } else if (s == 4 && m < 63) {
                // issue chunk 2m+2 -> buf0 (steps 8m+8..8m+11); prior readers
                // of buf0 finished before the bar that ended s==3.
                const long tof = (long)(8 * m + 8) * 3;
                #pragma unroll 1
                for (int e = ltid; e < 16 * 12; e += 160) {
                    int b = gid * 16 + e / 12, q = e - (e / 12) * 12;
                    cp_async16(xs_base + (u32)((b * XROW + q * 4) * 4),
                               x4 + (long)(b0 + b) * 1536 + tof + q);
                }
                cp_commit();
            }

            const int cur  = s & 1;          // compile-time after unroll
            const int nxt  = cur ^ 1;
            const int bufi = s >> 2;
            const int tt   = s & 3;

            const float* xb = &xs[bufi][tt * 12];
            const float* hb = &hbuf[cur][0];
            float* hn = &hbuf[nxt][0];

            float gA[4], gB[4];
            #pragma unroll
            for (int j = 0; j < 4; j++)
                gemv2((const u64*)(xb + (q4 + j) * XROW),
                      (const u64*)(hb + (q4 + j) * LSTM_H),
                      w0, w1, binit0, binit1, gA[j], gB[j]);

            // ---- exchange + epilogue, pairs p=0 (j 0/2) and p=1 (j 1/3) ----
            #pragma unroll
            for (int p = 0; p < 2; p++) {
                float sendA = gh ? gA[p]     : gA[2 + p];
                float sendB = gh ? gB[p]     : gB[2 + p];
                float ownA  = gh ? gA[2 + p] : gA[p];
                float ownB  = gh ? gB[2 + p] : gB[p];
                float recvA = __shfl_xor_sync(0xffffffffu, sendA, 1);
                float recvB = __shfl_xor_sync(0xffffffffu, sendB, 1);
                float gi = gh ? recvA : ownA;
                float gg = gh ? recvB : ownB;
                float gf = gh ? ownA  : recvA;
                float go = gh ? ownB  : recvB;
                float c  = p ? c1 : c0;
                c = sigA(gf) * c + sigA(gi) * tanhA(gg);
                if (p) c1 = c; else c0 = c;
                hn[(q4 + 2 * gh + p) * LSTM_H + u] = sigA(go) * tanhA(c);
            }

            // before the bar that precedes first read of a freshly filled
            // buffer, certify this thread's outstanding chunk landed; the bar
            // then certifies it for all threads.
            if (s == 3 || (s == 7 && m < 63)) cp_wait<0>();
            group_bar(barid);
        }
    }

    // ---- output Linear (final h in hbuf[0]: t=511 -> nxt=0; group-local) ----
    {
        const int bl = ltid / 10, k = ltid - (ltid / 10) * 10;  // 16 x 10
        const int b  = gid * 16 + bl;
        float sum = b_out[k];
        #pragma unroll
        for (int j = 0; j < LSTM_H; j++)
            sum = fmaf(hbuf[0][b * LSTM_H + j], w_out[k * LSTM_H + j], sum);
        out[(long)(b0 + b) * 10 + k] = sum;
    }
}

extern "C" void kernel_launch(void* const* d_in, const int* in_sizes, int n_in,
                              void* d_out, int out_size)
{
    const float* x     = (const float*)d_in[0];
    const float* w_ih  = (const float*)d_in[1];
    const float* w_hh  = (const float*)d_in[2];
    const float* b_ih  = (const float*)d_in[3];
    const float* b_hh  = (const float*)d_in[4];
    const float* w_out = (const float*)d_in[5];
    const float* b_out = (const float*)d_in[6];
    float* out = (float*)d_out;

    lstm_kernel<<<GRID, THREADS>>>(x, w_ih, w_hh, b_ih, b_hh, w_out, b_out, out);
}

// round 17
// speedup vs baseline: 1.6296x; 1.0005x over previous
#include <cuda_runtime.h>

// LSTM B=8192, T=512, I=12, H=20 (i,f,g,o), zero init; Linear(H->10) on h_T.
//
// R17 = R16 + strong phase stagger (x10 group-bars per phase, offsets
// ~0/500/1000/1500 cyc across the 4 barrier domains per SM) so one domain's
// MUFU-bound epilogue phase overlaps another's fma-bound GEMV phase within
// each SMSP. Everything else identical to R16:
//  - TCH=4 double-buffer (buf = s>>2), XROW=52, merged staging barriers
//    (cp_wait at s==3/s==7 before the regular step bar; issue at s==4/s==0).
//  - Thread = 2 gate rows x 1 unit x 4 batches, 32 u64 weights in regs;
//    partner (lane^1) holds the other 2 gates, combined via shfl.xor(1).
//  - Block 320 thr = 2 independent 160-thr groups (named barriers), BPB=32,
//    grid=256, __launch_bounds__(320,2). 8-step fully unrolled body.

#define LSTM_H   20
#define LSTM_I   12
#define LSTM_T   512
#define BPB      32
#define THREADS  320
#define GRID     256
#define XROW     52    // floats per batch row in xs (208B, 16B-aligned)

typedef unsigned long long u64;
typedef unsigned int       u32;

__device__ __forceinline__ u64 pack2(float lo, float hi) {
    u64 r; asm("mov.b64 %0, {%1, %2};" : "=l"(r) : "f"(lo), "f"(hi)); return r;
}
__device__ __forceinline__ void unpack2(u64 v, float& lo, float& hi) {
    asm("mov.b64 {%0, %1}, %2;" : "=f"(lo), "=f"(hi) : "l"(v));
}
__device__ __forceinline__ u64 fma2(u64 a, u64 b, u64 c) {
    u64 r; asm("fma.rn.f32x2 %0, %1, %2, %3;" : "=l"(r) : "l"(a), "l"(b), "l"(c));
    return r;
}
__device__ __forceinline__ float hadd2(u64 v) {
    float lo, hi; unpack2(v, lo, hi); return lo + hi;
}
__device__ __forceinline__ float tanhA(float x) {
    float y; asm("tanh.approx.f32 %0, %1;" : "=f"(y) : "f"(x)); return y;
}
__device__ __forceinline__ float sigA(float x) {
    return fmaf(tanhA(0.5f * x), 0.5f, 0.5f);
}
__device__ __forceinline__ void cp_async16(u32 smem_dst, const void* gsrc) {
    asm volatile("cp.async.ca.shared.global [%0], [%1], 16;\n"
                 :: "r"(smem_dst), "l"(gsrc) : "memory");
}
__device__ __forceinline__ void cp_commit() {
    asm volatile("cp.async.commit_group;\n" ::: "memory");
}
template<int N>
__device__ __forceinline__ void cp_wait() {
    asm volatile("cp.async.wait_group %0;\n" :: "n"(N) : "memory");
}
__device__ __forceinline__ void group_bar(int id) {
    asm volatile("bar.sync %0, %1;" :: "r"(id), "r"(160) : "memory");
}

// GEMV for one batch: 2 gate rows, bias folded into acc init.
__device__ __forceinline__ void gemv2(const u64* __restrict__ xr,
                                      const u64* __restrict__ hr,
                                      const u64* w0, const u64* w1,
                                      u64 binit0, u64 binit1,
                                      float& ga, float& gb)
{
    u64 a0 = binit0, a1 = binit1;
    #pragma unroll
    for (int k = 0; k < 6; k += 2) {
        ulonglong2 xv = *(const ulonglong2*)(xr + k);
        a0 = fma2(w0[k], xv.x, a0); a0 = fma2(w0[k+1], xv.y, a0);
        a1 = fma2(w1[k], xv.x, a1); a1 = fma2(w1[k+1], xv.y, a1);
    }
    #pragma unroll
    for (int k = 0; k < 10; k += 2) {
        ulonglong2 hv = *(const ulonglong2*)(hr + k);
        a0 = fma2(w0[6+k], hv.x, a0); a0 = fma2(w0[6+k+1], hv.y, a0);
        a1 = fma2(w1[6+k], hv.x, a1); a1 = fma2(w1[6+k+1], hv.y, a1);
    }
    ga = hadd2(a0);
    gb = hadd2(a1);
}

__global__ void __launch_bounds__(THREADS, 2)
lstm_kernel(const float* __restrict__ x,
            const float* __restrict__ w_ih,
            const float* __restrict__ w_hh,
            const float* __restrict__ b_ih,
            const float* __restrict__ b_hh,
            const float* __restrict__ w_out,
            const float* __restrict__ b_out,
            float* __restrict__ out)
{
    __shared__ __align__(16) float wcomb[80 * 32];           // 10240 B
    __shared__ __align__(16) float hbuf[2][BPB * LSTM_H];    //  5120 B
    __shared__ __align__(16) float xs[2][BPB * XROW];        // 13312 B

    const int tid  = threadIdx.x;
    const int gid  = tid / 160;          // group 0/1 (owns 16 batches)
    const int ltid = tid - gid * 160;
    const int quad = tid / 40;           // 0..7 (global)
    const int r    = tid % 40;
    const int u    = r >> 1;             // unit 0..19
    const int gh   = r & 1;              // 0 -> (i,g), 1 -> (f,o)
    const int b0   = blockIdx.x * BPB;
    const int q4   = quad * 4;
    const int barid = 1 + gid;

    const int row0 = gh ? (20 + u) : u;          // f : i
    const int row1 = gh ? (60 + u) : (40 + u);   // o : g

    // ---- stage combined weight rows into SMEM ----
    for (int i = tid; i < 80 * LSTM_I; i += THREADS) {
        int rr = i / LSTM_I, k = i - rr * LSTM_I;
        wcomb[rr * 32 + k] = w_ih[i];
    }
    for (int i = tid; i < 80 * LSTM_H; i += THREADS) {
        int rr = i / LSTM_H, k = i - rr * LSTM_H;
        wcomb[rr * 32 + 12 + k] = w_hh[i];
    }
    for (int i = tid; i < BPB * LSTM_H; i += THREADS) hbuf[0][i] = 0.f;

    const u64 binit0 = pack2(b_ih[row0] + b_hh[row0], 0.f);
    const u64 binit1 = pack2(b_ih[row1] + b_hh[row1], 0.f);

    // ---- cp.async: chunk0 -> xs[0], chunk1 -> xs[1] (group-local 16 batches) ----
    const float4* x4 = (const float4*)x;
    const u32 xs_base = (u32)__cvta_generic_to_shared(&xs[0][0]);
    {
        #pragma unroll 1
        for (int e = ltid; e < 16 * 12; e += 160) {
            int b = gid * 16 + e / 12, q = e - (e / 12) * 12;
            cp_async16(xs_base + (u32)((b * XROW + q * 4) * 4),
                       x4 + (long)(b0 + b) * 1536 + q);
        }
        cp_commit();
        #pragma unroll 1
        for (int e = ltid; e < 16 * 12; e += 160) {
            int b = gid * 16 + e / 12, q = e - (e / 12) * 12;
            cp_async16(xs_base + (u32)((BPB * XROW + b * XROW + q * 4) * 4),
                       x4 + (long)(b0 + b) * 1536 + 12 + q);
        }
        cp_commit();
    }
    cp_wait<1>();          // chunk 0 landed
    __syncthreads();       // wcomb + hbuf + chunk0 visible

    // ---- this thread's 2 gate rows into registers (32 u64 = 64 regs) ----
    u64 w0[16], w1[16];
    {
        const u64* p0 = (const u64*)&wcomb[row0 * 32];
        const u64* p1 = (const u64*)&wcomb[row1 * 32];
        #pragma unroll
        for (int k = 0; k < 16; k++) { w0[k] = p0[k]; w1[k] = p1[k]; }
    }

    // ---- strong phase stagger of the 4 barrier domains per SM ----
    // offsets ~0/500/1000/1500 cyc so epilogue (MUFU) phases of one domain
    // overlap GEMV (fma) phases of another within each SMSP.
    {
        const int phase = ((blockIdx.x & 1) << 1) | gid;   // 0..3
        for (int s = 0; s < phase * 10; s++) group_bar(barid);
    }

    float c0 = 0.f, c1 = 0.f;   // my 2 owned batches: q4+2*gh, q4+2*gh+1

    // ---- main loop: 64 iterations x 8 steps (2 chunks), fully unrolled ----
    #pragma unroll 1
    for (int m = 0; m < 64; m++) {
        #pragma unroll
        for (int s = 0; s < 8; s++) {
            // chunk issue points (step bars provide cross-thread ordering)
            if (s == 0 && m > 0) {
                const long tof = (long)(8 * m + 4) * 3;   // chunk 2m+1 -> buf1
                #pragma unroll 1
                for (int e = ltid; e < 16 * 12; e += 160) {
                    int b = gid * 16 + e / 12, q = e - (e / 12) * 12;
                    cp_async16(xs_base + (u32)((BPB * XROW + b * XROW + q * 4) * 4),
                               x4 + (long)(b0 + b) * 1536 + tof + q);
                }
                cp_commit();
            } else if (s == 4 && m < 63) {
                const long tof = (long)(8 * m + 8) * 3;   // chunk 2m+2 -> buf0
                #pragma unroll 1
                for (int e = ltid; e < 16 * 12; e += 160) {
                    int b = gid * 16 + e / 12, q = e - (e / 12) * 12;
                    cp_async16(xs_base + (u32)((b * XROW + q * 4) * 4),
                               x4 + (long)(b0 + b) * 1536 + tof + q);
                }
                cp_commit();
            }

            const int cur  = s & 1;          // compile-time after unroll
            const int nxt  = cur ^ 1;
            const int bufi = s >> 2;
            const int tt   = s & 3;

            const float* xb = &xs[bufi][tt * 12];
            const float* hb = &hbuf[cur][0];
            float* hn = &hbuf[nxt][0];

            float gA[4], gB[4];
            #pragma unroll
            for (int j = 0; j < 4; j++)
                gemv2((const u64*)(xb + (q4 + j) * XROW),
                      (const u64*)(hb + (q4 + j) * LSTM_H),
                      w0, w1, binit0, binit1, gA[j], gB[j]);

            // ---- exchange + epilogue, pairs p=0 (j 0/2) and p=1 (j 1/3) ----
            #pragma unroll
            for (int p = 0; p < 2; p++) {
                float sendA = gh ? gA[p]     : gA[2 + p];
                float sendB = gh ? gB[p]     : gB[2 + p];
                float ownA  = gh ? gA[2 + p] : gA[p];
                float ownB  = gh ? gB[2 + p] : gB[p];
                float recvA = __shfl_xor_sync(0xffffffffu, sendA, 1);
                float recvB = __shfl_xor_sync(0xffffffffu, sendB, 1);
                float gi = gh ? recvA : ownA;
                float gg = gh ? recvB : ownB;
                float gf = gh ? ownA  : recvA;
                float go = gh ? ownB  : recvB;
                float c  = p ? c1 : c0;
                c = sigA(gf) * c + sigA(gi) * tanhA(gg);
                if (p) c1 = c; else c0 = c;
                hn[(q4 + 2 * gh + p) * LSTM_H + u] = sigA(go) * tanhA(c);
            }

            if (s == 3 || (s == 7 && m < 63)) cp_wait<0>();
            group_bar(barid);
        }
    }

    // ---- output Linear (final h in hbuf[0]: t=511 -> nxt=0; group-local) ----
    {
        const int bl = ltid / 10, k = ltid - (ltid / 10) * 10;  // 16 x 10
        const int b  = gid * 16 + bl;
        float sum = b_out[k];
        #pragma unroll
        for (int j = 0; j < LSTM_H; j++)
            sum = fmaf(hbuf[0][b * LSTM_H + j], w_out[k * LSTM_H + j], sum);
        out[(long)(b0 + b) * 10 + k] = sum;
    }
}

extern "C" void kernel_launch(void* const* d_in, const int* in_sizes, int n_in,
                              void* d_out, int out_size)
{
    const float* x     = (const float*)d_in[0];
    const float* w_ih  = (const float*)d_in[1];
    const float* w_hh  = (const float*)d_in[2];
    const float* b_ih  = (const float*)d_in[3];
    const float* b_hh  = (const float*)d_in[4];
    const float* w_out = (const float*)d_in[5];
    const float* b_out = (const float*)d_in[6];
    float* out = (float*)d_out;

    lstm_kernel<<<GRID, THREADS>>>(x, w_ih, w_hh, b_ih, b_hh, w_out, b_out, out);
}